// round 13
// baseline (speedup 1.0000x reference)
#include <cuda_runtime.h>
#include <cuda_fp16.h>
#include <mma.h>
#include <cstdint>

namespace wm = nvcuda::wmma;
#define THREADS 512
#define SCALE 0.17677669529663687f

#define OFF_ACT  0         // half [128][264]
#define OFF_QH   67584     // half [128][264]
#define OFF_D0   135168    // 18432
#define OFF_D1   153600    // 18432
#define OFF_KVH  172032    // half [128][72]  (K/V, then O_h in place)
#define OFF_P    190464    // half [2][128][24]
#define OFF_SCR  202752    // float [16][16][20]
#define SMEM_BYTES 223232

typedef wm::fragment<wm::matrix_a, 16, 16, 16, __half, wm::row_major> FA;
typedef wm::fragment<wm::matrix_b, 16, 16, 16, __half, wm::row_major> FBr;
typedef wm::fragment<wm::matrix_b, 16, 16, 16, __half, wm::col_major> FBc;
typedef wm::fragment<wm::accumulator, 16, 16, 16, float> FC;

// 32 uniform slots of 9216 halfs.
// 0-7: wq chunk [32k][264n]; 8+6p+s: s0,s1 K [128k][72n]; s2,s3 V; s4,s5 wo [32k][264n]
__device__ __align__(16) __half g_stage[32 * 9216];

__global__ void prep_kernel(const float* __restrict__ wq, const float* __restrict__ wkv,
                            const float* __restrict__ wo) {
    int idx = blockIdx.x * blockDim.x + threadIdx.x;
    if (idx >= 32 * 9216) return;
    int item = idx / 9216, rem = idx % 9216;
    float v = 0.f;
    if (item < 8) {
        if (rem < 8448) { int kk = rem / 264, n = rem % 264;
            if (n < 256) v = wq[(item * 32 + kk) * 256 + n]; }
    } else {
        int t = item - 8, p = t / 6, s = t % 6;
        if (s < 4) {
            int kk = rem / 72, n = rem % 72;
            if (n < 64) {
                int k = (s & 1) * 128 + kk;
                int col = (s < 2) ? (64 * p + n) : (256 + 64 * p + n);
                v = wkv[k * 512 + col];
            }
        } else if (rem < 8448) {
            int kk = rem / 264, n = rem % 264;
            if (n < 256) v = wo[(64 * p + (s - 4) * 32 + kk) * 256 + n];
        }
    }
    g_stage[idx] = __float2half(v);
}

static __device__ __forceinline__ uint32_t s2u(const void* p) {
    uint32_t a;
    asm("{ .reg .u64 t; cvta.to.shared.u64 t, %1; cvt.u32.u64 %0, t; }" : "=r"(a) : "l"(p));
    return a;
}
#define CPCOMMIT() asm volatile("cp.async.commit_group;")
#define CPWAIT1()  asm volatile("cp.async.wait_group 1;")
#define CPWAIT0()  asm volatile("cp.async.wait_group 0;")

static __device__ void issue(int item, uint32_t sb) {
    uint32_t dst = sb + ((item & 1) ? OFF_D1 : OFF_D0);
    const char* src = (const char*)(g_stage + (size_t)item * 9216);
    for (int o = threadIdx.x * 16; o < 18432; o += THREADS * 16)
        asm volatile("cp.async.cg.shared.global [%0], [%1], 16;" :: "r"(dst + o), "l"(src + o));
    CPCOMMIT();
}

static __device__ void wb16(const FC& c, float* scr, __half* dst, int ldst,
                            const float* bias, int bcol) {
    wm::store_matrix_sync(scr, c, 20, wm::mem_row_major);
    __syncwarp();
    int lane = threadIdx.x & 31, r = lane >> 1, c0 = (lane & 1) * 8;
    __half hh[8];
#pragma unroll
    for (int e = 0; e < 8; e++) {
        float v = scr[r * 20 + c0 + e];
        if (bias) v += __ldg(bias + bcol + c0 + e);
        hh[e] = __float2half(v);
    }
    *(uint4*)(dst + r * ldst + c0) = *(uint4*)hh;
    __syncwarp();
}

// register-buffered transpose (2-way max conflict) + LN, 512 threads
static __device__ void load_ln(const float* __restrict__ src, __half* ACT,
                               const float* __restrict__ nw, int w0, int h0, int b) {
    const int lane = threadIdx.x & 31, warp = threadIdx.x >> 5;
    const int j = lane & 3, g = lane >> 2;
    for (int it = warp; it < 32; it += 16) {
        int c0 = (it >> 2) * 32, r = it & 3;
        int cbase = c0 + 8 * j;
        float4 buf[8];
#pragma unroll
        for (int s = 0; s < 8; s++)
            buf[s] = *(const float4*)(src +
                ((size_t)(b * 256 + cbase + s) * 384 + (h0 + r)) * 384 + w0 + 4 * g);
        int t0 = g * 16 + r * 4;
#pragma unroll
        for (int k = 0; k < 4; k++) {
            __half hh[8];
#pragma unroll
            for (int s = 0; s < 8; s++) {
                float v = (k == 0) ? buf[s].x : (k == 1) ? buf[s].y
                        : (k == 2) ? buf[s].z : buf[s].w;
                hh[s] = __float2half(v);
            }
            *(uint4*)(ACT + (t0 + k) * 264 + cbase) = *(uint4*)hh;
        }
    }
    __syncthreads();
    // LN: 4 threads per row (128 rows x 4 quarters of 64 ch)
    int row = threadIdx.x >> 2, c0 = (threadIdx.x & 3) * 64;
    __half* rp = ACT + row * 264 + c0;
    float s = 0.f, s2 = 0.f;
#pragma unroll
    for (int jj = 0; jj < 8; jj++) {
        uint4 u = *(uint4*)(rp + jj * 8);
        __half* hp = (__half*)&u;
#pragma unroll
        for (int e = 0; e < 8; e++) { float v = __half2float(hp[e]); s += v; s2 += v * v; }
    }
    s  += __shfl_xor_sync(0xffffffffu, s, 1);
    s2 += __shfl_xor_sync(0xffffffffu, s2, 1);
    s  += __shfl_xor_sync(0xffffffffu, s, 2);
    s2 += __shfl_xor_sync(0xffffffffu, s2, 2);
    float mean = s * (1.f / 256.f), var = s2 * (1.f / 256.f) - mean * mean;
    float rstd = rsqrtf(var + 1e-5f);
#pragma unroll
    for (int jj = 0; jj < 8; jj++) {
        uint4 u = *(uint4*)(rp + jj * 8);
        __half* hp = (__half*)&u;
#pragma unroll
        for (int e = 0; e < 8; e++)
            hp[e] = __float2half((__half2float(hp[e]) - mean) * rstd * __ldg(nw + c0 + jj * 8 + e));
        *(uint4*)(rp + jj * 8) = u;
    }
}

__global__ void __launch_bounds__(THREADS, 1)
xattn_kernel(const float* __restrict__ x, const float* __restrict__ cond,
             const float* __restrict__ n1w, const float* __restrict__ n2w,
             const float* __restrict__ bq, const float* __restrict__ bkv,
             const float* __restrict__ bo, const float* __restrict__ btab,
             float* __restrict__ out)
{
    extern __shared__ char sm[];
    const int tid = threadIdx.x, lane = tid & 31, warp = tid >> 5;
    const int w0 = blockIdx.x * 32, h0 = blockIdx.y * 4, b = blockIdx.z;
    uint32_t sb = s2u(sm);
    __half* ACT = (__half*)(sm + OFF_ACT);
    __half* QH  = (__half*)(sm + OFF_QH);
    __half* KVH = (__half*)(sm + OFF_KVH);   // K/V, then O_h in place
    __half* P   = (__half*)(sm + OFF_P);
    float* myscr = (float*)(sm + OFF_SCR) + warp * 320;
    const __half* DB[2] = { (const __half*)(sm + OFF_D0), (const __half*)(sm + OFF_D1) };

    int nit = 2;
    issue(0, sb); issue(1, sb);

    load_ln(cond, ACT, n1w, w0, h0, b);
    __syncthreads();

    const int mr = warp >> 2, nc = warp & 3;      // 32x64 tiling (Q, O): 4x4 grid
    const int mrk = warp >> 1, nck = warp & 1;    // 16x32 tiling (K, V): 8x2 grid
    const int win = warp >> 1, hh = warp & 1;     // attention: (window, head)

    // ===== Q projection =====
    {
        FC qa[8];
#pragma unroll
        for (int f = 0; f < 8; f++) wm::fill_fragment(qa[f], 0.0f);
        for (int kc = 0; kc < 8; kc++) {
            CPWAIT1(); __syncthreads();
            const __half* buf = DB[kc & 1];
#pragma unroll
            for (int s2 = 0; s2 < 2; s2++) {
                FA a2[2]; FBr b4[4];
#pragma unroll
                for (int i = 0; i < 2; i++)
                    wm::load_matrix_sync(a2[i], ACT + (mr * 32 + i * 16) * 264 + kc * 32 + s2 * 16, 264);
#pragma unroll
                for (int i = 0; i < 4; i++)
                    wm::load_matrix_sync(b4[i], buf + (s2 * 16) * 264 + nc * 64 + i * 16, 264);
#pragma unroll
                for (int fr = 0; fr < 2; fr++)
#pragma unroll
                    for (int fc = 0; fc < 4; fc++)
                        wm::mma_sync(qa[fr * 4 + fc], a2[fr], b4[fc], qa[fr * 4 + fc]);
            }
            __syncthreads();
            issue(nit, sb); nit++;
        }
#pragma unroll
        for (int f = 0; f < 8; f++) {
            int fr = f >> 2, fc = f & 3;
            wb16(qa[f], myscr, QH + (mr * 32 + fr * 16) * 264 + nc * 64 + fc * 16, 264,
                 bq, nc * 64 + fc * 16);
        }
    }
    __syncthreads();

    load_ln(x, ACT, n2w, w0, h0, b);
    __syncthreads();

    FC oacc[8];
#pragma unroll
    for (int f = 0; f < 8; f++) wm::fill_fragment(oacc[f], 0.0f);

    for (int p = 0; p < 4; p++) {
        // ---- K projection: [128][64], 16x32 tiles ----
        {
            FC ka[2];
#pragma unroll
            for (int f = 0; f < 2; f++) wm::fill_fragment(ka[f], 0.0f);
            for (int kr = 0; kr < 2; kr++) {
                CPWAIT1(); __syncthreads();
                const __half* buf = DB[kr];
#pragma unroll
                for (int s2 = 0; s2 < 8; s2++) {
                    FA a1; FBr b2[2];
                    wm::load_matrix_sync(a1, ACT + (mrk * 16) * 264 + kr * 128 + s2 * 16, 264);
#pragma unroll
                    for (int i = 0; i < 2; i++)
                        wm::load_matrix_sync(b2[i], buf + (s2 * 16) * 72 + nck * 32 + i * 16, 72);
#pragma unroll
                    for (int i = 0; i < 2; i++)
                        wm::mma_sync(ka[i], a1, b2[i], ka[i]);
                }
                __syncthreads();
                issue(nit, sb); nit++;
            }
#pragma unroll
            for (int i = 0; i < 2; i++)
                wb16(ka[i], myscr, KVH + (mrk * 16) * 72 + nck * 32 + i * 16, 72,
                     bkv, 64 * p + nck * 32 + i * 16);
        }
        __syncthreads();

        // ---- scores + softmax: warp = (window, head) ----
        {
            FA a2[2]; FBc b2[2];
#pragma unroll
            for (int i = 0; i < 2; i++)
                wm::load_matrix_sync(a2[i], QH + (win * 16) * 264 + (2 * p + hh) * 32 + i * 16, 264);
#pragma unroll
            for (int i = 0; i < 2; i++)
                wm::load_matrix_sync(b2[i], KVH + (win * 16) * 72 + hh * 32 + i * 16, 72);
            FC sc;
            wm::fill_fragment(sc, 0.0f);
            wm::mma_sync(sc, a2[0], b2[0], sc);
            wm::mma_sync(sc, a2[1], b2[1], sc);
            wm::store_matrix_sync(myscr, sc, 20, wm::mem_row_major);
            __syncwarp();
            if (lane < 16) {
                float v[16], mx = -1e30f;
#pragma unroll
                for (int m = 0; m < 16; m++) {
                    int bi = ((lane >> 2) - (m >> 2) + 3) * 7 + ((lane & 3) - (m & 3) + 3);
                    v[m] = myscr[lane * 20 + m] * SCALE + __ldg(btab + bi);
                    mx = fmaxf(mx, v[m]);
                }
                float s = 0.f;
#pragma unroll
                for (int m = 0; m < 16; m++) { v[m] = __expf(v[m] - mx); s += v[m]; }
                float inv = 1.0f / s;
                __half* pr = P + hh * 3072 + (win * 16 + lane) * 24;
#pragma unroll
                for (int m = 0; m < 16; m++) pr[m] = __float2half(v[m] * inv);
            }
            __syncwarp();
        }

        // ---- V projection (overwrites K in KVH) ----
        {
            FC va[2];
#pragma unroll
            for (int f = 0; f < 2; f++) wm::fill_fragment(va[f], 0.0f);
            for (int kr = 0; kr < 2; kr++) {
                CPWAIT1(); __syncthreads();
                const __half* buf = DB[kr];
#pragma unroll
                for (int s2 = 0; s2 < 8; s2++) {
                    FA a1; FBr b2[2];
                    wm::load_matrix_sync(a1, ACT + (mrk * 16) * 264 + kr * 128 + s2 * 16, 264);
#pragma unroll
                    for (int i = 0; i < 2; i++)
                        wm::load_matrix_sync(b2[i], buf + (s2 * 16) * 72 + nck * 32 + i * 16, 72);
#pragma unroll
                    for (int i = 0; i < 2; i++)
                        wm::mma_sync(va[i], a1, b2[i], va[i]);
                }
                __syncthreads();
                issue(nit, sb); nit++;
            }
#pragma unroll
            for (int i = 0; i < 2; i++)
                wb16(va[i], myscr, KVH + (mrk * 16) * 72 + nck * 32 + i * 16, 72,
                     bkv, 256 + 64 * p + nck * 32 + i * 16);
        }
        __syncthreads();

        // ---- PV: warp = (window, head); O_h overwrites its V slice in KVH ----
        {
            FA pa;
            wm::load_matrix_sync(pa, P + hh * 3072 + (win * 16) * 24, 24);
#pragma unroll
            for (int i = 0; i < 2; i++) {
                FBr bv;
                wm::load_matrix_sync(bv, KVH + (win * 16) * 72 + hh * 32 + i * 16, 72);
                FC oh;
                wm::fill_fragment(oh, 0.0f);
                wm::mma_sync(oh, pa, bv, oh);
                wb16(oh, myscr, KVH + (win * 16) * 72 + hh * 32 + i * 16, 72, nullptr, 0);
            }
        }

        // ---- O accumulation: oacc += O_h(KVH) @ wo_pair ----
        CPWAIT0(); __syncthreads();
#pragma unroll
        for (int kk = 0; kk < 4; kk++) {
            const __half* buf = DB[kk >> 1];
            FA a2[2]; FBr b4[4];
#pragma unroll
            for (int i = 0; i < 2; i++)
                wm::load_matrix_sync(a2[i], KVH + (mr * 32 + i * 16) * 72 + kk * 16, 72);
#pragma unroll
            for (int i = 0; i < 4; i++)
                wm::load_matrix_sync(b4[i], buf + ((kk & 1) * 16) * 264 + nc * 64 + i * 16, 264);
#pragma unroll
            for (int fr = 0; fr < 2; fr++)
#pragma unroll
                for (int fc = 0; fc < 4; fc++)
                    wm::mma_sync(oacc[fr * 4 + fc], a2[fr], b4[fc], oacc[fr * 4 + fc]);
        }
        __syncthreads();
        if (nit < 32) { issue(nit, sb); issue(nit + 1, sb); nit += 2; }
    }

    // ===== epilogue: oacc -> ep[128][260], wide token-major reads, coalesced gmem =====
    float* ep = (float*)sm;
#pragma unroll
    for (int f = 0; f < 8; f++) {
        int fr = f >> 2, fc = f & 3;
        wm::store_matrix_sync(ep + (size_t)(mr * 32 + fr * 16) * 260 + nc * 64 + fc * 16,
                              oacc[f], 260, wm::mem_row_major);
    }
    __syncthreads();
    {
        const int j = lane & 3, g = lane >> 2;
        for (int it = warp; it < 32; it += 16) {
            int c0 = (it >> 2) * 32, r = it & 3;
            int cbase = c0 + 8 * j;
            int t0 = g * 16 + r * 4;
            float vr[4][8];
#pragma unroll
            for (int k = 0; k < 4; k++) {
                *(float4*)&vr[k][0] = *(float4*)(ep + (size_t)(t0 + k) * 260 + cbase);
                *(float4*)&vr[k][4] = *(float4*)(ep + (size_t)(t0 + k) * 260 + cbase + 4);
            }
#pragma unroll
            for (int s = 0; s < 8; s++) {
                int c = cbase + s;
                size_t off = ((size_t)(b * 256 + c) * 384 + (h0 + r)) * 384 + w0 + 4 * g;
                float4 vx = *(const float4*)(x + off);
                float bias_o = __ldg(bo + c);
                float4 vo;
                vo.x = vx.x + vr[0][s] + bias_o;
                vo.y = vx.y + vr[1][s] + bias_o;
                vo.z = vx.z + vr[2][s] + bias_o;
                vo.w = vx.w + vr[3][s] + bias_o;
                *(float4*)(out + off) = vo;
            }
        }
    }
}

extern "C" void kernel_launch(void* const* d_in, const int* in_sizes, int n_in,
                              void* d_out, int out_size) {
    const float* x    = (const float*)d_in[0];
    const float* cond = (const float*)d_in[1];
    const float* n1w  = (const float*)d_in[2];
    const float* n2w  = (const float*)d_in[3];
    const float* wq   = (const float*)d_in[4];
    const float* bq   = (const float*)d_in[5];
    const float* wkv  = (const float*)d_in[6];
    const float* bkv  = (const float*)d_in[7];
    const float* wo   = (const float*)d_in[8];
    const float* bo   = (const float*)d_in[9];
    const float* btab = (const float*)d_in[10];
    float* out = (float*)d_out;

    int B = in_sizes[0] / (256 * 384 * 384);

    prep_kernel<<<1152, 256>>>(wq, wkv, wo);

    cudaFuncSetAttribute(xattn_kernel, cudaFuncAttributeMaxDynamicSharedMemorySize, SMEM_BYTES);
    dim3 grid(12, 96, B);
    xattn_kernel<<<grid, THREADS, SMEM_BYTES>>>(x, cond, n1w, n2w, bq, bkv, bo, btab, out);
}

// round 16
// speedup vs baseline: 1.0268x; 1.0268x over previous
#include <cuda_runtime.h>
#include <cuda_fp16.h>
#include <mma.h>
#include <cstdint>

namespace wm = nvcuda::wmma;
#define THREADS 128
#define SCALE 0.17677669529663687f

#define OFF_ACT  0         // half [64][264] = 33792
#define OFF_QH   33792     // half [64][264]
#define OFF_D0   67584     // 9216
#define OFF_D1   76800     // 9216
#define OFF_KVH  86016     // half [64][72] (K/V, then O_h in place)
#define OFF_P    95232     // half [2][64][24]
#define OFF_SCR  101376    // float [4][16][20]
#define SMEM_BYTES 106496

typedef wm::fragment<wm::matrix_a, 16, 16, 16, __half, wm::row_major> FA;
typedef wm::fragment<wm::matrix_b, 16, 16, 16, __half, wm::row_major> FBr;
typedef wm::fragment<wm::matrix_b, 16, 16, 16, __half, wm::col_major> FBc;
typedef wm::fragment<wm::accumulator, 16, 16, 16, float> FC;

// 64 uniform slots of 4608 halfs (9216 B).
// slots 0-15: wq [16k][264n]; then per p (base 16+12p):
//   +0..3:  K  [64k][72n]  (k rows s*64)
//   +4..7:  V  [64k][72n]
//   +8..11: wo [16k][264n] (k rows 64p+s*16)
__device__ __align__(16) __half g_stage[64 * 4608];

__global__ void prep_kernel(const float* __restrict__ wq, const float* __restrict__ wkv,
                            const float* __restrict__ wo) {
    int idx = blockIdx.x * blockDim.x + threadIdx.x;
    if (idx >= 64 * 4608) return;
    int item = idx / 4608, rem = idx % 4608;
    float v = 0.f;
    if (item < 16) {
        if (rem < 4224) {
            int kk = rem / 264, n = rem % 264;
            if (n < 256) v = wq[(item * 16 + kk) * 256 + n];
        }
    } else {
        int t = item - 16, p = t / 12, s = t % 12;
        if (s < 8) {
            int kk = rem / 72, n = rem % 72;
            if (n < 64) {
                int k = (s & 3) * 64 + kk;
                int col = (s < 4) ? (64 * p + n) : (256 + 64 * p + n);
                v = wkv[k * 512 + col];
            }
        } else if (rem < 4224) {
            int kk = rem / 264, n = rem % 264;
            if (n < 256) v = wo[(64 * p + (s - 8) * 16 + kk) * 256 + n];
        }
    }
    g_stage[idx] = __float2half(v);
}

static __device__ __forceinline__ uint32_t s2u(const void* p) {
    uint32_t a;
    asm("{ .reg .u64 t; cvta.to.shared.u64 t, %1; cvt.u32.u64 %0, t; }" : "=r"(a) : "l"(p));
    return a;
}
#define CPCOMMIT() asm volatile("cp.async.commit_group;")
#define CPWAIT1()  asm volatile("cp.async.wait_group 1;")

// ALWAYS commits (even past the end) so wait_group-1 accounting stays uniform:
// at the final consume, the trailing EMPTY group is the one left in flight,
// guaranteeing the last real item has landed. (R15 bug: early return skipped
// the commit -> last wo slot could be consumed while still in flight.)
static __device__ void issue(int item, uint32_t sb) {
    if (item < 64) {
        uint32_t dst = sb + ((item & 1) ? OFF_D1 : OFF_D0);
        const char* src = (const char*)(g_stage + (size_t)item * 4608);
        for (int o = threadIdx.x * 16; o < 9216; o += THREADS * 16)
            asm volatile("cp.async.cg.shared.global [%0], [%1], 16;" :: "r"(dst + o), "l"(src + o));
    }
    CPCOMMIT();
}

static __device__ void wb16(const FC& c, float* scr, __half* dst, int ldst,
                            const float* bias, int bcol) {
    wm::store_matrix_sync(scr, c, 20, wm::mem_row_major);
    __syncwarp();
    int lane = threadIdx.x & 31, r = lane >> 1, c0 = (lane & 1) * 8;
    __half hh[8];
#pragma unroll
    for (int e = 0; e < 8; e++) {
        float v = scr[r * 20 + c0 + e];
        if (bias) v += __ldg(bias + bcol + c0 + e);
        hh[e] = __float2half(v);
    }
    *(uint4*)(dst + r * ldst + c0) = *(uint4*)hh;
    __syncwarp();
}

// register-buffered transpose (conflict-free 16B rows) + LN, 128 threads, 64 tokens
static __device__ void load_ln(const float* __restrict__ src, __half* ACT,
                               const float* __restrict__ nw, int w0, int h0, int b) {
    const int lane = threadIdx.x & 31, warp = threadIdx.x >> 5;
    const int j = lane & 7, g = lane >> 3;   // j: channel octet, g: window quad
    for (int it = warp; it < 16; it += 4) {
        int cb = it >> 2, r = it & 3;
        int cbase = cb * 64 + 8 * j;
        float4 buf[8];
#pragma unroll
        for (int s = 0; s < 8; s++)
            buf[s] = *(const float4*)(src +
                ((size_t)(b * 256 + cbase + s) * 384 + (h0 + r)) * 384 + w0 + 4 * g);
        int t0 = g * 16 + r * 4;
#pragma unroll
        for (int k = 0; k < 4; k++) {
            __half hh[8];
#pragma unroll
            for (int s = 0; s < 8; s++) {
                float v = (k == 0) ? buf[s].x : (k == 1) ? buf[s].y
                        : (k == 2) ? buf[s].z : buf[s].w;
                hh[s] = __float2half(v);
            }
            *(uint4*)(ACT + (t0 + k) * 264 + cbase) = *(uint4*)hh;
        }
    }
    __syncthreads();
    // LN: 2 threads per row (64 rows x 2 halves of 128 ch)
    int row = threadIdx.x >> 1, c0 = (threadIdx.x & 1) * 128;
    __half* rp = ACT + row * 264 + c0;
    float s = 0.f, s2 = 0.f;
#pragma unroll 4
    for (int jj = 0; jj < 16; jj++) {
        uint4 u = *(uint4*)(rp + jj * 8);
        __half* hp = (__half*)&u;
#pragma unroll
        for (int e = 0; e < 8; e++) { float v = __half2float(hp[e]); s += v; s2 += v * v; }
    }
    s  += __shfl_xor_sync(0xffffffffu, s, 1);
    s2 += __shfl_xor_sync(0xffffffffu, s2, 1);
    float mean = s * (1.f / 256.f), var = s2 * (1.f / 256.f) - mean * mean;
    float rstd = rsqrtf(var + 1e-5f);
#pragma unroll 4
    for (int jj = 0; jj < 16; jj++) {
        uint4 u = *(uint4*)(rp + jj * 8);
        __half* hp = (__half*)&u;
#pragma unroll
        for (int e = 0; e < 8; e++)
            hp[e] = __float2half((__half2float(hp[e]) - mean) * rstd * __ldg(nw + c0 + jj * 8 + e));
        *(uint4*)(rp + jj * 8) = u;
    }
}

__global__ void __launch_bounds__(THREADS, 2)
xattn_kernel(const float* __restrict__ x, const float* __restrict__ cond,
             const float* __restrict__ n1w, const float* __restrict__ n2w,
             const float* __restrict__ bq, const float* __restrict__ bkv,
             const float* __restrict__ bo, const float* __restrict__ btab,
             float* __restrict__ out)
{
    extern __shared__ char sm[];
    const int tid = threadIdx.x, lane = tid & 31, warp = tid >> 5;
    const int w0 = blockIdx.x * 16, h0 = blockIdx.y * 4, b = blockIdx.z;
    uint32_t sb = s2u(sm);
    __half* ACT = (__half*)(sm + OFF_ACT);
    __half* QH  = (__half*)(sm + OFF_QH);
    __half* KVH = (__half*)(sm + OFF_KVH);
    __half* P   = (__half*)(sm + OFF_P);
    float* myscr = (float*)(sm + OFF_SCR) + warp * 320;
    const __half* DB[2] = { (const __half*)(sm + OFF_D0), (const __half*)(sm + OFF_D1) };

    int nit = 2;
    issue(0, sb); issue(1, sb);

    load_ln(cond, ACT, n1w, w0, h0, b);
    __syncthreads();

    const int mrk = warp >> 1, nck = warp & 1;   // 32x32 tiling (K, V): 2x2 grid
    const int win = warp;                        // attention: warp = window

    // ===== Q projection: [64][256], warp tile 64x64 (1x4 grid) =====
    {
        FC qa[16];
#pragma unroll
        for (int f = 0; f < 16; f++) wm::fill_fragment(qa[f], 0.0f);
        for (int kc = 0; kc < 16; kc++) {
            CPWAIT1(); __syncthreads();
            const __half* buf = DB[kc & 1];
            FA a4[4]; FBr b4[4];
#pragma unroll
            for (int i = 0; i < 4; i++)
                wm::load_matrix_sync(a4[i], ACT + (i * 16) * 264 + kc * 16, 264);
#pragma unroll
            for (int i = 0; i < 4; i++)
                wm::load_matrix_sync(b4[i], buf + warp * 64 + i * 16, 264);
#pragma unroll
            for (int fr = 0; fr < 4; fr++)
#pragma unroll
                for (int fc = 0; fc < 4; fc++)
                    wm::mma_sync(qa[fr * 4 + fc], a4[fr], b4[fc], qa[fr * 4 + fc]);
            __syncthreads();
            issue(nit, sb); nit++;
        }
#pragma unroll
        for (int f = 0; f < 16; f++) {
            int fr = f >> 2, fc = f & 3;
            wb16(qa[f], myscr, QH + (fr * 16) * 264 + warp * 64 + fc * 16, 264,
                 bq, warp * 64 + fc * 16);
        }
    }
    __syncthreads();

    load_ln(x, ACT, n2w, w0, h0, b);
    __syncthreads();

    FC oacc[16];
#pragma unroll
    for (int f = 0; f < 16; f++) wm::fill_fragment(oacc[f], 0.0f);

    for (int p = 0; p < 4; p++) {
        // ---- K projection: [64][64], 32x32 tiles, 4 slots of 64k ----
        {
            FC ka[4];
#pragma unroll
            for (int f = 0; f < 4; f++) wm::fill_fragment(ka[f], 0.0f);
            for (int kr = 0; kr < 4; kr++) {
                CPWAIT1(); __syncthreads();
                const __half* buf = DB[nit & 1];
#pragma unroll
                for (int s2 = 0; s2 < 4; s2++) {
                    FA a2[2]; FBr b2[2];
#pragma unroll
                    for (int i = 0; i < 2; i++)
                        wm::load_matrix_sync(a2[i], ACT + (mrk * 32 + i * 16) * 264 + kr * 64 + s2 * 16, 264);
#pragma unroll
                    for (int i = 0; i < 2; i++)
                        wm::load_matrix_sync(b2[i], buf + (s2 * 16) * 72 + nck * 32 + i * 16, 72);
#pragma unroll
                    for (int fr = 0; fr < 2; fr++)
#pragma unroll
                        for (int fc = 0; fc < 2; fc++)
                            wm::mma_sync(ka[fr * 2 + fc], a2[fr], b2[fc], ka[fr * 2 + fc]);
                }
                __syncthreads();
                issue(nit, sb); nit++;
            }
#pragma unroll
            for (int f = 0; f < 4; f++) {
                int fr = f >> 1, fc = f & 1;
                wb16(ka[f], myscr, KVH + (mrk * 32 + fr * 16) * 72 + nck * 32 + fc * 16, 72,
                     bkv, 64 * p + nck * 32 + fc * 16);
            }
        }
        __syncthreads();

        // ---- scores + softmax: warp = window, 2 heads ----
        for (int hh = 0; hh < 2; hh++) {
            FA a2[2]; FBc b2[2];
#pragma unroll
            for (int i = 0; i < 2; i++)
                wm::load_matrix_sync(a2[i], QH + (win * 16) * 264 + (2 * p + hh) * 32 + i * 16, 264);
#pragma unroll
            for (int i = 0; i < 2; i++)
                wm::load_matrix_sync(b2[i], KVH + (win * 16) * 72 + hh * 32 + i * 16, 72);
            FC sc;
            wm::fill_fragment(sc, 0.0f);
            wm::mma_sync(sc, a2[0], b2[0], sc);
            wm::mma_sync(sc, a2[1], b2[1], sc);
            wm::store_matrix_sync(myscr, sc, 20, wm::mem_row_major);
            __syncwarp();
            if (lane < 16) {
                float v[16], mx = -1e30f;
#pragma unroll
                for (int m = 0; m < 16; m++) {
                    int bi = ((lane >> 2) - (m >> 2) + 3) * 7 + ((lane & 3) - (m & 3) + 3);
                    v[m] = myscr[lane * 20 + m] * SCALE + __ldg(btab + bi);
                    mx = fmaxf(mx, v[m]);
                }
                float s = 0.f;
#pragma unroll
                for (int m = 0; m < 16; m++) { v[m] = __expf(v[m] - mx); s += v[m]; }
                float inv = 1.0f / s;
                __half* pr = P + hh * 1536 + (win * 16 + lane) * 24;
#pragma unroll
                for (int m = 0; m < 16; m++) pr[m] = __float2half(v[m] * inv);
            }
            __syncwarp();
        }

        // ---- V projection (overwrites K in KVH) ----
        {
            FC va[4];
#pragma unroll
            for (int f = 0; f < 4; f++) wm::fill_fragment(va[f], 0.0f);
            for (int kr = 0; kr < 4; kr++) {
                CPWAIT1(); __syncthreads();
                const __half* buf = DB[nit & 1];
#pragma unroll
                for (int s2 = 0; s2 < 4; s2++) {
                    FA a2[2]; FBr b2[2];
#pragma unroll
                    for (int i = 0; i < 2; i++)
                        wm::load_matrix_sync(a2[i], ACT + (mrk * 32 + i * 16) * 264 + kr * 64 + s2 * 16, 264);
#pragma unroll
                    for (int i = 0; i < 2; i++)
                        wm::load_matrix_sync(b2[i], buf + (s2 * 16) * 72 + nck * 32 + i * 16, 72);
#pragma unroll
                    for (int fr = 0; fr < 2; fr++)
#pragma unroll
                        for (int fc = 0; fc < 2; fc++)
                            wm::mma_sync(va[fr * 2 + fc], a2[fr], b2[fc], va[fr * 2 + fc]);
                }
                __syncthreads();
                issue(nit, sb); nit++;
            }
#pragma unroll
            for (int f = 0; f < 4; f++) {
                int fr = f >> 1, fc = f & 1;
                wb16(va[f], myscr, KVH + (mrk * 32 + fr * 16) * 72 + nck * 32 + fc * 16, 72,
                     bkv, 256 + 64 * p + nck * 32 + fc * 16);
            }
        }
        __syncthreads();

        // ---- PV: warp = window; O_h overwrites its V rows in KVH ----
        for (int hh = 0; hh < 2; hh++) {
            FA pa;
            wm::load_matrix_sync(pa, P + hh * 1536 + (win * 16) * 24, 24);
#pragma unroll
            for (int i = 0; i < 2; i++) {
                FBr bv;
                wm::load_matrix_sync(bv, KVH + (win * 16) * 72 + hh * 32 + i * 16, 72);
                FC oh;
                wm::fill_fragment(oh, 0.0f);
                wm::mma_sync(oh, pa, bv, oh);
                wb16(oh, myscr, KVH + (win * 16) * 72 + hh * 32 + i * 16, 72, nullptr, 0);
            }
        }

        // ---- O accumulation: oacc += O_h(KVH) @ wo, 4 slots of 16k ----
        for (int ws = 0; ws < 4; ws++) {
            CPWAIT1(); __syncthreads();
            const __half* buf = DB[nit & 1];
            FA a4[4]; FBr b4[4];
#pragma unroll
            for (int i = 0; i < 4; i++)
                wm::load_matrix_sync(a4[i], KVH + (i * 16) * 72 + ws * 16, 72);
#pragma unroll
            for (int i = 0; i < 4; i++)
                wm::load_matrix_sync(b4[i], buf + warp * 64 + i * 16, 264);
#pragma unroll
            for (int fr = 0; fr < 4; fr++)
#pragma unroll
                for (int fc = 0; fc < 4; fc++)
                    wm::mma_sync(oacc[fr * 4 + fc], a4[fr], b4[fc], oacc[fr * 4 + fc]);
            __syncthreads();
            issue(nit, sb); nit++;
        }
    }

    // ===== epilogue: oacc -> ep[64][260], wide token-major reads, coalesced gmem =====
    float* ep = (float*)sm;
#pragma unroll
    for (int f = 0; f < 16; f++) {
        int fr = f >> 2, fc = f & 3;
        wm::store_matrix_sync(ep + (size_t)(fr * 16) * 260 + warp * 64 + fc * 16,
                              oacc[f], 260, wm::mem_row_major);
    }
    __syncthreads();
    {
        const int j = lane & 7, g = lane >> 3;
        for (int it = warp; it < 16; it += 4) {
            int cb = it >> 2, r = it & 3;
            int cbase = cb * 64 + 8 * j;
            int t0 = g * 16 + r * 4;
            float vr[4][8];
#pragma unroll
            for (int k = 0; k < 4; k++) {
                *(float4*)&vr[k][0] = *(float4*)(ep + (size_t)(t0 + k) * 260 + cbase);
                *(float4*)&vr[k][4] = *(float4*)(ep + (size_t)(t0 + k) * 260 + cbase + 4);
            }
#pragma unroll
            for (int s = 0; s < 8; s++) {
                int c = cbase + s;
                size_t off = ((size_t)(b * 256 + c) * 384 + (h0 + r)) * 384 + w0 + 4 * g;
                float4 vx = *(const float4*)(x + off);
                float bias_o = __ldg(bo + c);
                float4 vo;
                vo.x = vx.x + vr[0][s] + bias_o;
                vo.y = vx.y + vr[1][s] + bias_o;
                vo.z = vx.z + vr[2][s] + bias_o;
                vo.w = vx.w + vr[3][s] + bias_o;
                *(float4*)(out + off) = vo;
            }
        }
    }
}

extern "C" void kernel_launch(void* const* d_in, const int* in_sizes, int n_in,
                              void* d_out, int out_size) {
    const float* x    = (const float*)d_in[0];
    const float* cond = (const float*)d_in[1];
    const float* n1w  = (const float*)d_in[2];
    const float* n2w  = (const float*)d_in[3];
    const float* wq   = (const float*)d_in[4];
    const float* bq   = (const float*)d_in[5];
    const float* wkv  = (const float*)d_in[6];
    const float* bkv  = (const float*)d_in[7];
    const float* wo   = (const float*)d_in[8];
    const float* bo   = (const float*)d_in[9];
    const float* btab = (const float*)d_in[10];
    float* out = (float*)d_out;

    int B = in_sizes[0] / (256 * 384 * 384);

    prep_kernel<<<1152, 256>>>(wq, wkv, wo);

    cudaFuncSetAttribute(xattn_kernel, cudaFuncAttributeMaxDynamicSharedMemorySize, SMEM_BYTES);
    dim3 grid(24, 96, B);
    xattn_kernel<<<grid, THREADS, SMEM_BYTES>>>(x, cond, n1w, n2w, bq, bkv, bo, btab, out);
}